// round 4
// baseline (speedup 1.0000x reference)
#include <cuda_runtime.h>
#include <cuda_bf16.h>
#include <math.h>
#include <stdint.h>

#define BB   128
#define TL   2048
#define HH   200
#define HP   256
#define NT   16        // t-tiles per batch row (2048/128)
#define KP2  224       // padded K (14 k16 steps)
#define NP   208       // padded N (h)
#define NKCH 7         // k chunks of 32
#define BSTRH 232      // smem/gmem B,A row stride in halves (= 464 B, 16B-mult)
#define BSTRW 116      // row stride in 32-bit words

// ---------------- device scratch ----------------
__device__ float d_qp[BB * HP];                       // q@Wa.T + ba + bua (padded)
__device__ float d_Vap[HP];                           // Va padded (0 beyond 200)
__device__ __align__(16) unsigned short d_Bbf[NP * BSTRH]; // Ua bf16, smem-identical layout
__device__ float d_mloc[BB * NT];
__device__ float d_zloc[BB * NT];
__device__ float d_ctxp[BB * NT * HH];

// ---------------- helpers ----------------
__device__ __forceinline__ float tanha(float x) {
    float y; asm("tanh.approx.f32 %0, %1;" : "=f"(y) : "f"(x)); return y;
}
__device__ __forceinline__ float sigf(float x) { return 1.0f / (1.0f + __expf(-x)); }
__device__ __forceinline__ uint32_t smem_u32(const void* p) {
    uint32_t a;
    asm("{ .reg .u64 t; cvta.to.shared.u64 t, %1; cvt.u32.u64 %0, t; }" : "=r"(a) : "l"(p));
    return a;
}
__device__ __forceinline__ void cp16(uint32_t dst, const void* src) {
    asm volatile("cp.async.ca.shared.global [%0], [%1], 16;" :: "r"(dst), "l"(src) : "memory");
}
__device__ __forceinline__ uint32_t packbf(float lo, float hi) {
    uint32_t r; asm("cvt.rn.bf16x2.f32 %0, %1, %2;" : "=r"(r) : "f"(hi), "f"(lo)); return r;
}
__device__ __forceinline__ void mma_bf16(float* c, const uint32_t* a, uint32_t b0, uint32_t b1) {
    asm volatile("mma.sync.aligned.m16n8k16.row.col.f32.bf16.bf16.f32 "
                 "{%0,%1,%2,%3}, {%4,%5,%6,%7}, {%8,%9}, {%0,%1,%2,%3};"
                 : "+f"(c[0]), "+f"(c[1]), "+f"(c[2]), "+f"(c[3])
                 : "r"(a[0]), "r"(a[1]), "r"(a[2]), "r"(a[3]), "r"(b0), "r"(b1));
}

// SMEM layout (bytes)
#define SM_QP  0
#define SM_VA  1024
#define SM_RED 2048
#define SM_W   3072
#define SM_SCL 3584
#define SM_A   4096
#define SM_B   (SM_A + 128 * BSTRH * 2)     // 4096 + 59392 = 63488
#define SMEM_SZ (SM_B + NP * BSTRH * 2)     // 63488 + 96512 = 160000

extern __shared__ char sm_dyn[];

// ---------------- 1) setup: qp, B bf16 (final layout), Va ----------------
__global__ void setup_kernel(const float* __restrict__ h0,
                             const float* __restrict__ Wa,
                             const float* __restrict__ ba,
                             const float* __restrict__ Ua,
                             const float* __restrict__ bua,
                             const float* __restrict__ Va) {
    int blk = blockIdx.x;
    int tid = threadIdx.x;
    if (blk < BB) {
        const float* q = h0 + blk * HH;
        for (int h = tid; h < HP; h += blockDim.x) {
            float v = 0.0f;
            if (h < HH) {
                float acc = ba[h] + bua[h];
                const float* w = Wa + h * HH;
                #pragma unroll 4
                for (int k = 0; k < HH; k++) acc += w[k] * q[k];
                v = acc;
            }
            d_qp[blk * HP + h] = v;
        }
    } else {
        int n0 = (blk - BB) * 26;                 // 8 blocks x 26 rows = 208
        for (int idx = tid; idx < 26 * BSTRH; idx += blockDim.x) {
            int n = n0 + idx / BSTRH, k = idx % BSTRH;
            float v = (n < HH && k < HH) ? Ua[n * HH + k] : 0.0f;
            __nv_bfloat16 bv = __float2bfloat16(v);
            d_Bbf[n * BSTRH + k] = *(unsigned short*)&bv;
        }
        if (blk == BB) {
            for (int h = tid; h < HP; h += blockDim.x)
                d_Vap[h] = (h < HH) ? Va[h] : 0.0f;
        }
    }
}

// ---------------- 2) scores + flash partial context (fused) ----------------
__device__ __forceinline__ void load_chunk(float4* st, const float* encb, int ch) {
    int tid = threadIdx.x;
    #pragma unroll
    for (int it = 0; it < 4; it++) {
        int i = tid + it * 256;
        int m = i >> 3, kq = i & 7;
        int k = ch * 32 + kq * 4;
        if (k < HH) st[it] = *(const float4*)(encb + (long)m * HH + k);
        else        st[it] = make_float4(0.f, 0.f, 0.f, 0.f);
    }
}
__device__ __forceinline__ void sts_chunk(char* smem, const float4* st, int ch) {
    int tid = threadIdx.x;
    #pragma unroll
    for (int it = 0; it < 4; it++) {
        int i = tid + it * 256;
        int m = i >> 3, kq = i & 7;
        int k = ch * 32 + kq * 4;
        uint2 p;
        p.x = packbf(st[it].x, st[it].y);
        p.y = packbf(st[it].z, st[it].w);
        *(uint2*)(smem + SM_A + ((long)m * BSTRH + k) * 2) = p;
    }
}

__global__ void __launch_bounds__(256, 1)
scores_mma_kernel(const float* __restrict__ enc) {
    char* smem = sm_dyn;
    uint32_t sb = smem_u32(smem);
    int tid  = threadIdx.x;
    int lane = tid & 31;
    int wid  = tid >> 5;
    int wm   = wid & 3;
    int wn   = wid >> 2;
    int g    = lane >> 2;
    int c    = lane & 3;
    int tile = blockIdx.x;
    int b    = blockIdx.y;
    int t0   = tile * 128;

    // one-shot B copy (gmem layout == smem layout)
    {
        uint32_t dstB = sb + SM_B;
        const char* srcB = (const char*)d_Bbf;
        for (int i = tid; i < (NP * BSTRH * 2) / 16; i += 256)
            cp16(dstB + i * 16, srcB + i * 16);
        asm volatile("cp.async.commit_group;" ::: "memory");
    }
    ((float*)(smem + SM_QP))[tid] = d_qp[b * HP + tid];
    ((float*)(smem + SM_VA))[tid] = d_Vap[tid];

    const float* encb = enc + ((long)b * TL + t0) * HH;

    float acc[2][13][4];
    #pragma unroll
    for (int mt = 0; mt < 2; mt++)
        #pragma unroll
        for (int nt = 0; nt < 13; nt++)
            #pragma unroll
            for (int j = 0; j < 4; j++) acc[mt][nt][j] = 0.0f;

    float4 st[4];
    load_chunk(st, encb, 0);

    const uint32_t* A32 = (const uint32_t*)(smem + SM_A);
    const uint32_t* B32 = (const uint32_t*)(smem + SM_B);
    int arow = wm * 32 + g;
    int nbase = wn * 104 + g;

    #pragma unroll 1
    for (int ch = 0; ch < NKCH; ch++) {
        sts_chunk(smem, st, ch);
        if (ch + 1 < NKCH) load_chunk(st, encb, ch + 1);
        if (ch == 0) asm volatile("cp.async.wait_group 0;" ::: "memory");
        __syncthreads();

        #pragma unroll
        for (int ks = 0; ks < 2; ks++) {
            int kw = (ch * 32 + ks * 16) >> 1;
            uint32_t a[2][4];
            #pragma unroll
            for (int mt = 0; mt < 2; mt++) {
                int r = arow + mt * 16;
                a[mt][0] = A32[(long)r * BSTRW + kw + c];
                a[mt][1] = A32[(long)(r + 8) * BSTRW + kw + c];
                a[mt][2] = A32[(long)r * BSTRW + kw + c + 4];
                a[mt][3] = A32[(long)(r + 8) * BSTRW + kw + c + 4];
            }
            #pragma unroll
            for (int nt = 0; nt < 13; nt++) {
                int n = nbase + nt * 8;
                uint32_t b0 = B32[(long)n * BSTRW + kw + c];
                uint32_t b1 = B32[(long)n * BSTRW + kw + c + 4];
                mma_bf16(acc[0][nt], a[0], b0, b1);
                mma_bf16(acc[1][nt], a[1], b0, b1);
            }
        }
    }

    // ---- epilogue: scores then flash partials ----
    const float* qpS = (const float*)(smem + SM_QP);
    const float* VaS = (const float*)(smem + SM_VA);
    float rs[4] = {0.f, 0.f, 0.f, 0.f};
    #pragma unroll
    for (int mt = 0; mt < 2; mt++) {
        #pragma unroll
        for (int nt = 0; nt < 13; nt++) {
            int h0 = wn * 104 + nt * 8 + c * 2;
            float va0 = VaS[h0], va1 = VaS[h0 + 1];
            float q0 = qpS[h0], q1 = qpS[h0 + 1];
            float* cc = acc[mt][nt];
            rs[mt * 2 + 0] += va0 * tanha(q0 + cc[0]) + va1 * tanha(q1 + cc[1]);
            rs[mt * 2 + 1] += va0 * tanha(q0 + cc[2]) + va1 * tanha(q1 + cc[3]);
        }
    }
    #pragma unroll
    for (int j = 0; j < 4; j++) {
        rs[j] += __shfl_xor_sync(0xffffffffu, rs[j], 1);
        rs[j] += __shfl_xor_sync(0xffffffffu, rs[j], 2);
    }
    float* red = (float*)(smem + SM_RED);
    float* w   = (float*)(smem + SM_W);
    float* scl = (float*)(smem + SM_SCL);
    __syncthreads();
    if (c == 0) {
        int r0 = wm * 32 + g;
        red[wn * 128 + r0]      = rs[0];
        red[wn * 128 + r0 + 8]  = rs[1];
        red[wn * 128 + r0 + 16] = rs[2];
        red[wn * 128 + r0 + 24] = rs[3];
    }
    __syncthreads();
    float sv = 0.0f;
    if (tid < 128) sv = red[tid] + red[128 + tid];   // bva shift cancels in softmax
    __syncthreads();
    red[tid] = (tid < 128) ? sv : -1e30f;
    __syncthreads();
    for (int s = 128; s; s >>= 1) {
        if (tid < s) red[tid] = fmaxf(red[tid], red[tid + s]);
        __syncthreads();
    }
    float mloc = red[0];
    __syncthreads();
    float wv = 0.0f;
    if (tid < 128) { wv = __expf(sv - mloc); w[tid] = wv; }
    red[tid] = wv;
    __syncthreads();
    for (int s = 128; s; s >>= 1) {
        if (tid < s) red[tid] += red[tid + s];
        __syncthreads();
    }
    if (tid == 0) { scl[0] = red[0]; }
    __syncthreads();

    // partial context from resident bf16 A tile
    if (tid < 100) {
        float a0 = 0.f, a1 = 0.f;
        #pragma unroll 4
        for (int t = 0; t < 128; t++) {
            uint32_t v = A32[(long)t * BSTRW + tid];
            float wt = w[t];
            a0 += wt * __uint_as_float(v << 16);
            a1 += wt * __uint_as_float(v & 0xFFFF0000u);
        }
        d_ctxp[((long)b * NT + tile) * HH + 2 * tid]     = a0;
        d_ctxp[((long)b * NT + tile) * HH + 2 * tid + 1] = a1;
    }
    if (tid == 0) {
        d_mloc[b * NT + tile] = mloc;
        d_zloc[b * NT + tile] = scl[0];
    }
}

// ---------------- 3) decoder: combine + 5 LSTM+MLP steps, 4 b per block ----------------
__global__ void __launch_bounds__(256) decoder_kernel(
        const float* __restrict__ x,
        const float* __restrict__ h0,
        const float* __restrict__ c0,
        const float* __restrict__ W_ih,
        const float* __restrict__ W_hh,
        const float* __restrict__ b_ih,
        const float* __restrict__ b_hh,
        const float* __restrict__ W1, const float* __restrict__ b1,
        const float* __restrict__ W2, const float* __restrict__ b2,
        const float* __restrict__ W3, const float* __restrict__ b3,
        float* __restrict__ out) {
    __shared__ float ctx4[4][HH];
    __shared__ float h04[4][HH];
    __shared__ float gb4[4][800];
    __shared__ float coef[NT];
    __shared__ float zinv_s;
    __shared__ float r[HH];
    __shared__ float s1[100];
    __shared__ float s2[64];
    __shared__ float xb;
    int tid = threadIdx.x;
    int bs0 = blockIdx.x * 4;

    // combine flash partials -> ctx4
    for (int bl = 0; bl < 4; bl++) {
        int b = bs0 + bl;
        if (tid == 0) {
            float M = -1e30f;
            for (int i = 0; i < NT; i++) M = fmaxf(M, d_mloc[b * NT + i]);
            float Z = 0.f;
            for (int i = 0; i < NT; i++) {
                float cc = __expf(d_mloc[b * NT + i] - M);
                coef[i] = cc;
                Z += cc * d_zloc[b * NT + i];
            }
            zinv_s = 1.0f / Z;
        }
        __syncthreads();
        if (tid < HH) {
            float s = 0.f;
            #pragma unroll
            for (int i = 0; i < NT; i++)
                s += coef[i] * d_ctxp[((long)b * NT + i) * HH + tid];
            ctx4[bl][tid] = s * zinv_s;
        }
        __syncthreads();
    }
    for (int i = tid; i < 4 * HH; i += 256)
        h04[i / HH][i % HH] = h0[(bs0 + i / HH) * HH + i % HH];
    __syncthreads();

    // gbase for 4 b's, weights read once
    for (int g = tid; g < 800; g += 256) {
        float bias = b_ih[g] + b_hh[g];
        float a0 = bias, a1 = bias, a2 = bias, a3 = bias;
        const float* wh = W_hh + g * HH;
        #pragma unroll 4
        for (int k = 0; k < HH; k++) {
            float wv = wh[k];
            a0 += wv * h04[0][k]; a1 += wv * h04[1][k];
            a2 += wv * h04[2][k]; a3 += wv * h04[3][k];
        }
        const float* wi = W_ih + g * 201 + 1;
        #pragma unroll 4
        for (int k = 0; k < HH; k++) {
            float wv = wi[k];
            a0 += wv * ctx4[0][k]; a1 += wv * ctx4[1][k];
            a2 += wv * ctx4[2][k]; a3 += wv * ctx4[3][k];
        }
        gb4[0][g] = a0; gb4[1][g] = a1; gb4[2][g] = a2; gb4[3][g] = a3;
    }
    __syncthreads();

    for (int bl = 0; bl < 4; bl++) {
        int b = bs0 + bl;
        if (tid == 0) xb = x[b];
        __syncthreads();
        for (int step = 0; step < 5; step++) {
            if (tid < HH) {
                float xv = xb;
                float gi = gb4[bl][tid]       + W_ih[tid * 201]         * xv;
                float gf = gb4[bl][200 + tid] + W_ih[(200 + tid) * 201] * xv;
                float gg = gb4[bl][400 + tid] + W_ih[(400 + tid) * 201] * xv;
                float go = gb4[bl][600 + tid] + W_ih[(600 + tid) * 201] * xv;
                float cp = c0[b * HH + tid];
                float cn = sigf(gf) * cp + sigf(gi) * tanhf(gg);
                float hn = sigf(go) * tanhf(cn);
                r[tid] = fmaxf(hn, 0.0f);
            }
            __syncthreads();
            if (tid < 100) {
                float acc = b1[tid];
                const float* wr = W1 + tid * HH;
                #pragma unroll 4
                for (int k = 0; k < HH; k++) acc += wr[k] * r[k];
                s1[tid] = fmaxf(acc, 0.0f);
            }
            __syncthreads();
            if (tid < 50) {
                float acc = b2[tid];
                const float* wr = W2 + tid * 100;
                #pragma unroll 4
                for (int k = 0; k < 100; k++) acc += wr[k] * s1[k];
                s2[tid] = fmaxf(acc, 0.0f);
            }
            __syncthreads();
            if (tid == 0) {
                float acc = b3[0];
                #pragma unroll
                for (int k = 0; k < 50; k++) acc += W3[k] * s2[k];
                out[b * 5 + step] = acc;
                xb = acc;
            }
            __syncthreads();
        }
    }
}

// ---------------- launch ----------------
extern "C" void kernel_launch(void* const* d_in, const int* in_sizes, int n_in,
                              void* d_out, int out_size) {
    const float* x    = (const float*)d_in[0];
    const float* h0   = (const float*)d_in[1];
    const float* c0   = (const float*)d_in[2];
    const float* enc  = (const float*)d_in[3];
    const float* Wa   = (const float*)d_in[4];
    const float* ba   = (const float*)d_in[5];
    const float* Ua   = (const float*)d_in[6];
    const float* bua  = (const float*)d_in[7];
    const float* Va   = (const float*)d_in[8];
    const float* bva  = (const float*)d_in[9];
    const float* W_ih = (const float*)d_in[10];
    const float* W_hh = (const float*)d_in[11];
    const float* b_ih = (const float*)d_in[12];
    const float* b_hh = (const float*)d_in[13];
    const float* W1   = (const float*)d_in[14];
    const float* b1   = (const float*)d_in[15];
    const float* W2   = (const float*)d_in[16];
    const float* b2   = (const float*)d_in[17];
    const float* W3   = (const float*)d_in[18];
    const float* b3   = (const float*)d_in[19];
    float* out = (float*)d_out;
    (void)bva;

    cudaFuncSetAttribute(scores_mma_kernel,
                         cudaFuncAttributeMaxDynamicSharedMemorySize, SMEM_SZ);

    setup_kernel<<<BB + 8, 256>>>(h0, Wa, ba, Ua, bua, Va);
    scores_mma_kernel<<<dim3(NT, BB), 256, SMEM_SZ>>>(enc);
    decoder_kernel<<<BB / 4, 256>>>(x, h0, c0, W_ih, W_hh, b_ih, b_hh,
                                    W1, b1, W2, b2, W3, b3, out);
}